// round 10
// baseline (speedup 1.0000x reference)
#include <cuda_runtime.h>
#include <cstdint>

#define Wd 512
#define BATCH 16
#define NPIX (Wd * Wd)
#define NTOT (BATCH * NPIX)
#define PADW 520
#define PADH 516
#define PADN (PADW * PADH)
#define INV_CELL 2.56f  /* 1 / (200/512) */
#define ROWS_PB 4
#define FILL_BYTES ((ROWS_PB + 4) * PADW * 4)

// Padded tm1 (= terrain - 1) buffers, zero borders.
// Logical (i,j) lives at pad[(i+2)*PADW + (j+4)].
__device__ __align__(16) float g_padA[BATCH * PADN];
__device__ __align__(16) float g_padB[BATCH * PADN];
__device__ __align__(16) float2 g_sw[NTOT];     // x=sed y=wat
__device__ __align__(16) float g_vel[NTOT];
__device__ float g_par[8];

__global__ void init_kernel(const float* __restrict__ in,
                            const float* rr, const float* ev, const float* mh,
                            const float* he, const float* gr, const float* kc,
                            const float* di, const float* de) {
    if (blockIdx.x == 0 && threadIdx.x == 0) {
        g_par[0] = fmaxf(*rr, 0.0f);            // relu(rain_rate)
        g_par[1] = *he;                         // height_epsilon
        g_par[2] = *mh;                         // min_height_delta
        g_par[3] = fmaxf(*kc, 0.0f) * INV_CELL; // relu(kc)/CELL_W
        g_par[4] = *di;                         // dissolving_rate
        g_par[5] = *de;                         // deposition_rate
        g_par[6] = 1.0f - fmaxf(*ev, 0.0f);     // 1 - relu(evap)
        g_par[7] = fmaxf(*gr, 0.0f) * INV_CELL; // relu(g)/CELL_W
    }
    int row = blockIdx.x;            // 0 .. BATCH*PADH-1
    int b = row / PADH;
    int pi = row - b * PADH;
    int pj = threadIdx.x;            // 0 .. 519
    int pidx = b * PADN + pi * PADW + pj;
    if (pi >= 2 && pi < 2 + Wd && pj >= 4 && pj < 4 + Wd) {
        int i = pi - 2, j = pj - 4;
        int cidx = b * NPIX + i * Wd + j;
        float t0 = (1.0f - in[cidx]) * 0.5f;
        g_padA[pidx] = t0 - 1.0f;            // reference's tm1, exactly
        g_sw[cidx] = make_float2(0.0f, 0.0f);
        g_vel[cidx] = 0.0f;
    } else {
        // borders must be zero; interiors of B are written by step 0 before read
        g_padA[pidx] = 0.0f;
        g_padB[pidx] = 0.0f;
    }
}

__device__ __forceinline__ uint32_t smem_u32(const void* p) {
    uint32_t a;
    asm("{ .reg .u64 t; cvta.to.shared.u64 t, %1; cvt.u32.u64 %0, t; }"
        : "=r"(a) : "l"(p));
    return a;
}

template <bool LAST>
__global__ void __launch_bounds__(256, 7)
step_kernel(const float* __restrict__ pin, float* __restrict__ pout,
            const float* __restrict__ rain, float* __restrict__ outp) {
    // padded rows i0..i0+7 (logical i0-2..i0+5)
    __shared__ __align__(16) float sm[(ROWS_PB + 4) * PADW];
    __shared__ __align__(8) unsigned long long mbar;

    int blk = blockIdx.x;
    int b = blk >> 7;            // batch (128 blocks per batch)
    int i0 = (blk & 127) << 2;   // first of 4 grid rows
    int t = threadIdx.x;
    int r = t >> 6;              // row within block (0..3)
    int q = t & 63;              // lane-position within row
    int i = i0 + r;

    uint32_t mb = smem_u32(&mbar);
    if (t == 0) {
        asm volatile("mbarrier.init.shared.b64 [%0], 1;" :: "r"(mb) : "memory");
    }
    __syncthreads();
    if (t == 0) {
        asm volatile("mbarrier.arrive.expect_tx.shared.b64 _, [%0], %1;"
                     :: "r"(mb), "r"(FILL_BYTES) : "memory");
        const float* src = pin + (size_t)b * PADN + (size_t)i0 * PADW;
        asm volatile(
            "cp.async.bulk.shared::cluster.global.mbarrier::complete_tx::bytes "
            "[%0], [%1], %2, [%3];"
            :: "r"(smem_u32(sm)), "l"(src), "r"(FILL_BYTES), "r"(mb) : "memory");
    }

    int cbase = b * NPIX + i * Wd;
    const float* rrow = rain + i * Wd;

    const float4* parv = reinterpret_cast<const float4*>(g_par);
    float4 pA = parv[0];  // x=rain_rate' y=heps z=minhd w=kc'
    float4 pB = parv[1];  // x=dis y=dep z=evap' w=grav'

    // ---- first half's state loads, front-batched to overlap the TMA fill ----
    float2 sw_[4];
    float v_[4], rn_[4];
#pragma unroll
    for (int k = 0; k < 4; ++k) {
        int jj = q + (k << 6);
        sw_[k] = g_sw[cbase + jj];
        v_[k]  = g_vel[cbase + jj];
        rn_[k] = rrow[jj];
    }

    // only warp 0 waits on the TMA mbarrier (HW-sleep); everyone else parks at the barrier
    if (t < 32) {
        uint32_t done = 0;
        while (!done) {
            asm volatile(
                "{ .reg .pred p; mbarrier.try_wait.parity.shared.b64 p, [%1], 0, 0x989680; "
                "selp.u32 %0, 1, 0, p; }"
                : "=r"(done) : "r"(mb) : "memory");
        }
    }
    __syncthreads();

    const float* smc = sm + (r + 2) * PADW + 4;   // this row's center, logical col 0
    bool interior_i = (i > 0) && (i < Wd - 1);
    float rowsc = (i == 0) ? 1.1f : 0.9f;
    float fi = (float)i;
    float* porow = pout + (size_t)b * PADN + (size_t)(i + 2) * PADW + 4;

#pragma unroll
    for (int half = 0; half < 2; ++half) {
        if (half == 1) {
            // second half's state loads, front-batched
#pragma unroll
            for (int k = 0; k < 4; ++k) {
                int jj = q + ((k + 4) << 6);
                sw_[k] = g_sw[cbase + jj];
                v_[k]  = g_vel[cbase + jj];
                rn_[k] = rrow[jj];
            }
        }

#pragma unroll
        for (int k = 0; k < 4; ++k) {
            int jj = q + ((half * 4 + k) << 6);

            float tcm = smc[jj];   // tm1-space terrain

            float dx;
            if (interior_i) {
                dx = 0.5f * (smc[jj + PADW] - smc[jj - PADW]);
            } else {
                float tcf = tcm + 1.0f;
                dx = 0.5f * (tcf * rowsc - tcf);
            }

            float dy;
            if (jj == 0) {
                float tcf = tcm + 1.0f;
                dy = 0.5f * (tcf * 1.1f - tcf);
            } else if (jj == Wd - 1) {
                float tcf = tcm + 1.0f;
                dy = 0.5f * (tcf * 0.9f - tcf);
            } else {
                dy = 0.5f * (smc[jj + 1] - smc[jj - 1]);
            }

            float rinv = rsqrtf(dx * dx + dy * dy + 1e-11f);
            float fdx = dx * rinv;
            float fdy = dy * rinv;

            // bilinear gather — entirely from SMEM (logical rows i0-2..i0+5 staged)
            float fx = (float)jj - fdx;
            float fy = fi - fdy;
            float x0 = floorf(fx), y0 = floorf(fy);
            float wx = fx - x0, wy = fy - y0;
            int ix = (int)x0;
            int iy = (int)y0;

            const float* g = sm + (iy - i0 + 2) * PADW + (ix + 4);
            float g00 = g[0];
            float g10 = g[1];
            float g01 = g[PADW];
            float g11 = g[PADW + 1];
            // nbm = neighbor - 1 (bilerp of tm1, zero-padded)
            float nbm = (1.0f - wy) * ((1.0f - wx) * g00 + wx * g10)
                      + wy          * ((1.0f - wx) * g01 + wx * g11);

            float hd = tcm - nbm;
            float nhd = (hd > pA.y) ? fmaxf(hd, pA.z) : 0.0f;

            float s = sw_[k].x;
            float w = sw_[k].y + pA.x * rn_[k];

            float scap = nhd * pA.w * v_[k] * w;
            float first = fminf(fmaxf(-hd, 0.0f), s);
            float sdiff = s - scap;
            float third = (hd < 0.0f) ? 0.0f
                        : (fmaxf(sdiff * pB.y, 0.0f) - fmaxf(-sdiff * pB.x, 0.0f));
            float dep = fmaxf(-fmaxf(hd, 0.0f), first + third);

            float s2 = s - dep;
            float t2m = tcm + dep;    // = new terrain - 1

            // displace factor: r1+r2+r3 with column-boundary zeroing
            float ad = fabsf(fdy);
            float r2v = fmaxf(1.0f - ad, 0.0f);
            float fac = ad + r2v;
            if (jj == 0)        fac = fmaxf(-fdy, 0.0f) + r2v;  // t3 zeroed at col 0
            if (jj == Wd - 1)   fac = r2v + fmaxf(fdy, 0.0f);   // t1 zeroed at col W-1

            int cidx = cbase + jj;
            g_sw[cidx] = make_float2(fac * s2, (fac * w) * pB.z);
            g_vel[cidx] = pB.w * hd;
            if (LAST) {
                // relu(2 - 2*t2) - 1 == relu(-2*t2m) - 1
                outp[cidx] = fmaxf(-2.0f * t2m, 0.0f) - 1.0f;
            } else {
                porow[jj] = t2m;
            }
        }
    }
}

extern "C" void kernel_launch(void* const* d_in, const int* in_sizes, int n_in,
                              void* d_out, int out_size) {
    const float* input     = (const float*)d_in[0];
    const float* rainall   = (const float*)d_in[1];
    // d_in[2] (random_gradient) provably unused: factor == relu(1e-10 - mag) == 0 in fp32.
    const float* rain_rate = (const float*)d_in[3];
    const float* evap      = (const float*)d_in[4];
    const float* minhd     = (const float*)d_in[5];
    const float* heps      = (const float*)d_in[6];
    const float* grav      = (const float*)d_in[7];
    const float* kc        = (const float*)d_in[8];
    const float* dis       = (const float*)d_in[9];
    const float* depr      = (const float*)d_in[10];
    float* out = (float*)d_out;

    float *pA, *pB;
    cudaGetSymbolAddress((void**)&pA, g_padA);
    cudaGetSymbolAddress((void**)&pB, g_padB);

    init_kernel<<<BATCH * PADH, PADW>>>(input, rain_rate, evap, minhd, heps,
                                        grav, kc, dis, depr);

    for (int it = 0; it < 10; ++it) {
        const float* pin = (it & 1) ? pB : pA;
        float* pout      = (it & 1) ? pA : pB;
        const float* rain = rainall + (size_t)it * NPIX;
        if (it == 9) {
            step_kernel<true><<<BATCH * 128, 256>>>(pin, pout, rain, out);
        } else {
            step_kernel<false><<<BATCH * 128, 256>>>(pin, pout, rain, out);
        }
    }
}

// round 11
// speedup vs baseline: 1.0945x; 1.0945x over previous
#include <cuda_runtime.h>
#include <cstdint>

#define Wd 512
#define BATCH 16
#define NPIX (Wd * Wd)
#define NTOT (BATCH * NPIX)
#define PADW 520
#define PADH 516
#define PADN (PADW * PADH)
#define INV_CELL 2.56f  /* 1 / (200/512) */
#define ROWS_PB 4
#define FILL_BYTES ((ROWS_PB + 4) * PADW * 4)
#define RAIN_BYTES (ROWS_PB * Wd * 4)

// Padded tm1 (= terrain - 1) buffers, zero borders.
// Logical (i,j) lives at pad[(i+2)*PADW + (j+4)].
__device__ __align__(16) float g_padA[BATCH * PADN];
__device__ __align__(16) float g_padB[BATCH * PADN];
__device__ __align__(16) float2 g_sw[NTOT];     // x=sed y=wat
__device__ __align__(16) float g_vel[NTOT];
__device__ float g_par[8];

__global__ void init_kernel(const float* __restrict__ in,
                            const float* rr, const float* ev, const float* mh,
                            const float* he, const float* gr, const float* kc,
                            const float* di, const float* de) {
    if (blockIdx.x == 0 && threadIdx.x == 0) {
        g_par[0] = fmaxf(*rr, 0.0f);            // relu(rain_rate)
        g_par[1] = *he;                         // height_epsilon
        g_par[2] = *mh;                         // min_height_delta
        g_par[3] = fmaxf(*kc, 0.0f) * INV_CELL; // relu(kc)/CELL_W
        g_par[4] = *di;                         // dissolving_rate
        g_par[5] = *de;                         // deposition_rate
        g_par[6] = 1.0f - fmaxf(*ev, 0.0f);     // 1 - relu(evap)
        g_par[7] = fmaxf(*gr, 0.0f) * INV_CELL; // relu(g)/CELL_W
    }
    int row = blockIdx.x;            // 0 .. BATCH*PADH-1
    int b = row / PADH;
    int pi = row - b * PADH;
    int pj = threadIdx.x;            // 0 .. 519
    int pidx = b * PADN + pi * PADW + pj;
    if (pi >= 2 && pi < 2 + Wd && pj >= 4 && pj < 4 + Wd) {
        int i = pi - 2, j = pj - 4;
        int cidx = b * NPIX + i * Wd + j;
        float t0 = (1.0f - in[cidx]) * 0.5f;
        g_padA[pidx] = t0 - 1.0f;            // reference's tm1, exactly
        g_sw[cidx] = make_float2(0.0f, 0.0f);
        g_vel[cidx] = 0.0f;
    } else {
        // borders must be zero; interiors of B are written by step 0 before read
        g_padA[pidx] = 0.0f;
        g_padB[pidx] = 0.0f;
    }
}

__device__ __forceinline__ uint32_t smem_u32(const void* p) {
    uint32_t a;
    asm("{ .reg .u64 t; cvta.to.shared.u64 t, %1; cvt.u32.u64 %0, t; }"
        : "=r"(a) : "l"(p));
    return a;
}

template <bool LAST>
__global__ void __launch_bounds__(256)
step_kernel(const float* __restrict__ pin, float* __restrict__ pout,
            const float* __restrict__ rain, float* __restrict__ outp) {
    // padded rows i0..i0+7 (logical i0-2..i0+5)
    __shared__ __align__(16) float sm[(ROWS_PB + 4) * PADW];
    __shared__ __align__(16) float smr[ROWS_PB * Wd];   // rain rows i0..i0+3
    __shared__ __align__(8) unsigned long long mbar;

    int blk = blockIdx.x;
    int b = blk >> 7;            // batch (128 blocks per batch)
    int i0 = (blk & 127) << 2;   // first of 4 grid rows
    int t = threadIdx.x;
    int r = t >> 6;              // row within block (0..3)
    int q = t & 63;              // lane-position within row
    int i = i0 + r;

    uint32_t mb = smem_u32(&mbar);
    if (t == 0) {
        asm volatile("mbarrier.init.shared.b64 [%0], 1;" :: "r"(mb) : "memory");
    }
    __syncthreads();
    if (t == 0) {
        asm volatile("mbarrier.arrive.expect_tx.shared.b64 _, [%0], %1;"
                     :: "r"(mb), "r"(FILL_BYTES + RAIN_BYTES) : "memory");
        const float* src = pin + (size_t)b * PADN + (size_t)i0 * PADW;
        asm volatile(
            "cp.async.bulk.shared::cluster.global.mbarrier::complete_tx::bytes "
            "[%0], [%1], %2, [%3];"
            :: "r"(smem_u32(sm)), "l"(src), "r"(FILL_BYTES), "r"(mb) : "memory");
        const float* rsrc = rain + (size_t)i0 * Wd;
        asm volatile(
            "cp.async.bulk.shared::cluster.global.mbarrier::complete_tx::bytes "
            "[%0], [%1], %2, [%3];"
            :: "r"(smem_u32(smr)), "l"(rsrc), "r"(RAIN_BYTES), "r"(mb) : "memory");
    }

    int cbase = b * NPIX + i * Wd;

    const float4* parv = reinterpret_cast<const float4*>(g_par);
    float4 pA = parv[0];  // x=rain_rate' y=heps z=minhd w=kc'
    float4 pB = parv[1];  // x=dis y=dep z=evap' w=grav'

    // ---- first half's state loads, front-batched to overlap the TMA fills ----
    float2 sw_[4];
    float v_[4];
#pragma unroll
    for (int k = 0; k < 4; ++k) {
        int jj = q + (k << 6);
        sw_[k] = g_sw[cbase + jj];
        v_[k]  = g_vel[cbase + jj];
    }

    // only warp 0 waits on the TMA mbarrier (HW-sleep); everyone else parks at the barrier
    if (t < 32) {
        uint32_t done = 0;
        while (!done) {
            asm volatile(
                "{ .reg .pred p; mbarrier.try_wait.parity.shared.b64 p, [%1], 0, 0x989680; "
                "selp.u32 %0, 1, 0, p; }"
                : "=r"(done) : "r"(mb) : "memory");
        }
    }
    __syncthreads();

    const float* smc = sm + (r + 2) * PADW + 4;   // this row's center, logical col 0
    const float* smrr = smr + r * Wd;             // this row's rain
    bool interior_i = (i > 0) && (i < Wd - 1);
    float rowsc = (i == 0) ? 1.1f : 0.9f;
    float fi = (float)i;
    float* porow = pout + (size_t)b * PADN + (size_t)(i + 2) * PADW + 4;

#pragma unroll
    for (int half = 0; half < 2; ++half) {
        if (half == 1) {
            // second half's state loads, front-batched
#pragma unroll
            for (int k = 0; k < 4; ++k) {
                int jj = q + ((k + 4) << 6);
                sw_[k] = g_sw[cbase + jj];
                v_[k]  = g_vel[cbase + jj];
            }
        }

#pragma unroll
        for (int k = 0; k < 4; ++k) {
            int jj = q + ((half * 4 + k) << 6);

            float tcm = smc[jj];   // tm1-space terrain

            float dx;
            if (interior_i) {
                dx = 0.5f * (smc[jj + PADW] - smc[jj - PADW]);
            } else {
                float tcf = tcm + 1.0f;
                dx = 0.5f * (tcf * rowsc - tcf);
            }

            float dy;
            if (jj == 0) {
                float tcf = tcm + 1.0f;
                dy = 0.5f * (tcf * 1.1f - tcf);
            } else if (jj == Wd - 1) {
                float tcf = tcm + 1.0f;
                dy = 0.5f * (tcf * 0.9f - tcf);
            } else {
                dy = 0.5f * (smc[jj + 1] - smc[jj - 1]);
            }

            float rinv = rsqrtf(dx * dx + dy * dy + 1e-11f);
            float fdx = dx * rinv;
            float fdy = dy * rinv;

            // bilinear gather — entirely from SMEM (logical rows i0-2..i0+5 staged)
            float fx = (float)jj - fdx;
            float fy = fi - fdy;
            float x0 = floorf(fx), y0 = floorf(fy);
            float wx = fx - x0, wy = fy - y0;
            int ix = (int)x0;
            int iy = (int)y0;

            const float* g = sm + (iy - i0 + 2) * PADW + (ix + 4);
            float g00 = g[0];
            float g10 = g[1];
            float g01 = g[PADW];
            float g11 = g[PADW + 1];
            // nbm = neighbor - 1 (bilerp of tm1, zero-padded)
            float nbm = (1.0f - wy) * ((1.0f - wx) * g00 + wx * g10)
                      + wy          * ((1.0f - wx) * g01 + wx * g11);

            float hd = tcm - nbm;
            float nhd = (hd > pA.y) ? fmaxf(hd, pA.z) : 0.0f;

            float s = sw_[k].x;
            float w = sw_[k].y + pA.x * smrr[jj];

            float scap = nhd * pA.w * v_[k] * w;
            float first = fminf(fmaxf(-hd, 0.0f), s);
            float sdiff = s - scap;
            float third = (hd < 0.0f) ? 0.0f
                        : (fmaxf(sdiff * pB.y, 0.0f) - fmaxf(-sdiff * pB.x, 0.0f));
            float dep = fmaxf(-fmaxf(hd, 0.0f), first + third);

            float s2 = s - dep;
            float t2m = tcm + dep;    // = new terrain - 1

            // displace factor: r1+r2+r3 with column-boundary zeroing
            float ad = fabsf(fdy);
            float r2v = fmaxf(1.0f - ad, 0.0f);
            float fac = ad + r2v;
            if (jj == 0)        fac = fmaxf(-fdy, 0.0f) + r2v;  // t3 zeroed at col 0
            if (jj == Wd - 1)   fac = r2v + fmaxf(fdy, 0.0f);   // t1 zeroed at col W-1

            int cidx = cbase + jj;
            g_sw[cidx] = make_float2(fac * s2, (fac * w) * pB.z);
            g_vel[cidx] = pB.w * hd;
            if (LAST) {
                // relu(2 - 2*t2) - 1 == relu(-2*t2m) - 1
                outp[cidx] = fmaxf(-2.0f * t2m, 0.0f) - 1.0f;
            } else {
                porow[jj] = t2m;
            }
        }
    }
}

extern "C" void kernel_launch(void* const* d_in, const int* in_sizes, int n_in,
                              void* d_out, int out_size) {
    const float* input     = (const float*)d_in[0];
    const float* rainall   = (const float*)d_in[1];
    // d_in[2] (random_gradient) provably unused: factor == relu(1e-10 - mag) == 0 in fp32.
    const float* rain_rate = (const float*)d_in[3];
    const float* evap      = (const float*)d_in[4];
    const float* minhd     = (const float*)d_in[5];
    const float* heps      = (const float*)d_in[6];
    const float* grav      = (const float*)d_in[7];
    const float* kc        = (const float*)d_in[8];
    const float* dis       = (const float*)d_in[9];
    const float* depr      = (const float*)d_in[10];
    float* out = (float*)d_out;

    float *pA, *pB;
    cudaGetSymbolAddress((void**)&pA, g_padA);
    cudaGetSymbolAddress((void**)&pB, g_padB);

    init_kernel<<<BATCH * PADH, PADW>>>(input, rain_rate, evap, minhd, heps,
                                        grav, kc, dis, depr);

    for (int it = 0; it < 10; ++it) {
        const float* pin = (it & 1) ? pB : pA;
        float* pout      = (it & 1) ? pA : pB;
        const float* rain = rainall + (size_t)it * NPIX;
        if (it == 9) {
            step_kernel<true><<<BATCH * 128, 256>>>(pin, pout, rain, out);
        } else {
            step_kernel<false><<<BATCH * 128, 256>>>(pin, pout, rain, out);
        }
    }
}

// round 12
// speedup vs baseline: 1.1458x; 1.0469x over previous
#include <cuda_runtime.h>
#include <cstdint>

#define Wd 512
#define BATCH 16
#define NPIX (Wd * Wd)
#define NTOT (BATCH * NPIX)
#define PADW 520
#define PADH 516
#define PADN (PADW * PADH)
#define INV_CELL 2.56f  /* 1 / (200/512) */
#define ROWS_PB 4
#define FILL_BYTES ((ROWS_PB + 4) * PADW * 4)
#define RAIN_BYTES (ROWS_PB * Wd * 4)

// Padded tm1 (= terrain - 1) buffers, zero borders.
// Logical (i,j) lives at pad[(i+2)*PADW + (j+4)].
__device__ __align__(16) float g_padA[BATCH * PADN];
__device__ __align__(16) float g_padB[BATCH * PADN];
__device__ __align__(16) float2 g_sw[NTOT];     // x=sed y=wat
__device__ __align__(16) float g_vel[NTOT];
__device__ float g_par[8];

__global__ void init_kernel(const float* __restrict__ in,
                            const float* rr, const float* ev, const float* mh,
                            const float* he, const float* gr, const float* kc,
                            const float* di, const float* de) {
    if (blockIdx.x == 0 && threadIdx.x == 0) {
        g_par[0] = fmaxf(*rr, 0.0f);            // relu(rain_rate)
        g_par[1] = *he;                         // height_epsilon
        g_par[2] = *mh;                         // min_height_delta
        g_par[3] = fmaxf(*kc, 0.0f) * INV_CELL; // relu(kc)/CELL_W
        g_par[4] = *di;                         // dissolving_rate
        g_par[5] = *de;                         // deposition_rate
        g_par[6] = 1.0f - fmaxf(*ev, 0.0f);     // 1 - relu(evap)
        g_par[7] = fmaxf(*gr, 0.0f) * INV_CELL; // relu(g)/CELL_W
    }
    int row = blockIdx.x;            // 0 .. BATCH*PADH-1
    int b = row / PADH;
    int pi = row - b * PADH;
    int pj = threadIdx.x;            // 0 .. 519
    int pidx = b * PADN + pi * PADW + pj;
    if (pi >= 2 && pi < 2 + Wd && pj >= 4 && pj < 4 + Wd) {
        int i = pi - 2, j = pj - 4;
        int cidx = b * NPIX + i * Wd + j;
        float t0 = (1.0f - in[cidx]) * 0.5f;
        g_padA[pidx] = t0 - 1.0f;            // reference's tm1, exactly
        // g_sw / g_vel written unconditionally by step0_kernel
    } else {
        // borders must be zero; interiors of B are written by step 1 before read
        g_padA[pidx] = 0.0f;
        g_padB[pidx] = 0.0f;
    }
}

__device__ __forceinline__ uint32_t smem_u32(const void* p) {
    uint32_t a;
    asm("{ .reg .u64 t; cvta.to.shared.u64 t, %1; cvt.u32.u64 %0, t; }"
        : "=r"(a) : "l"(p));
    return a;
}

// Shared staging prologue: TMA of (ROWS_PB+4) padded terrain rows + ROWS_PB rain rows.
__device__ __forceinline__ void stage_tiles(const float* pin, const float* rain,
                                            int b, int i0, int t,
                                            float* sm, float* smr, uint32_t mb) {
    if (t == 0) {
        asm volatile("mbarrier.init.shared.b64 [%0], 1;" :: "r"(mb) : "memory");
    }
    __syncthreads();
    if (t == 0) {
        asm volatile("mbarrier.arrive.expect_tx.shared.b64 _, [%0], %1;"
                     :: "r"(mb), "r"(FILL_BYTES + RAIN_BYTES) : "memory");
        const float* src = pin + (size_t)b * PADN + (size_t)i0 * PADW;
        asm volatile(
            "cp.async.bulk.shared::cluster.global.mbarrier::complete_tx::bytes "
            "[%0], [%1], %2, [%3];"
            :: "r"(smem_u32(sm)), "l"(src), "r"(FILL_BYTES), "r"(mb) : "memory");
        const float* rsrc = rain + (size_t)i0 * Wd;
        asm volatile(
            "cp.async.bulk.shared::cluster.global.mbarrier::complete_tx::bytes "
            "[%0], [%1], %2, [%3];"
            :: "r"(smem_u32(smr)), "l"(rsrc), "r"(RAIN_BYTES), "r"(mb) : "memory");
    }
}

__device__ __forceinline__ void wait_tiles(int t, uint32_t mb) {
    // only warp 0 waits (HW-sleep); everyone else parks at the barrier
    if (t < 32) {
        uint32_t done = 0;
        while (!done) {
            asm volatile(
                "{ .reg .pred p; mbarrier.try_wait.parity.shared.b64 p, [%1], 0, 0x989680; "
                "selp.u32 %0, 1, 0, p; }"
                : "=r"(done) : "r"(mb) : "memory");
        }
    }
    __syncthreads();
}

// Gradient + bilinear gather (tm1-space). Returns hd; writes fdy.
__device__ __forceinline__ float grad_gather(const float* sm, const float* smc,
                                             int jj, int i, int i0,
                                             bool interior_i, float rowsc,
                                             float fi, float& fdy_out) {
    float tcm = smc[jj];

    float dx;
    if (interior_i) {
        dx = 0.5f * (smc[jj + PADW] - smc[jj - PADW]);
    } else {
        float tcf = tcm + 1.0f;
        dx = 0.5f * (tcf * rowsc - tcf);
    }

    float dy;
    if (jj == 0) {
        float tcf = tcm + 1.0f;
        dy = 0.5f * (tcf * 1.1f - tcf);
    } else if (jj == Wd - 1) {
        float tcf = tcm + 1.0f;
        dy = 0.5f * (tcf * 0.9f - tcf);
    } else {
        dy = 0.5f * (smc[jj + 1] - smc[jj - 1]);
    }

    float rinv = rsqrtf(dx * dx + dy * dy + 1e-11f);
    float fdx = dx * rinv;
    float fdy = dy * rinv;
    fdy_out = fdy;

    float fx = (float)jj - fdx;
    float fy = fi - fdy;
    float x0 = floorf(fx), y0 = floorf(fy);
    float wx = fx - x0, wy = fy - y0;
    int ix = (int)x0;
    int iy = (int)y0;

    const float* g = sm + (iy - i0 + 2) * PADW + (ix + 4);
    float g00 = g[0];
    float g10 = g[1];
    float g01 = g[PADW];
    float g11 = g[PADW + 1];
    float nbm = (1.0f - wy) * ((1.0f - wx) * g00 + wx * g10)
              + wy          * ((1.0f - wx) * g01 + wx * g11);

    return tcm - nbm;
}

__device__ __forceinline__ float disp_fac(float fdy, int jj) {
    float ad = fabsf(fdy);
    float r2v = fmaxf(1.0f - ad, 0.0f);
    float fac = ad + r2v;
    if (jj == 0)        fac = fmaxf(-fdy, 0.0f) + r2v;  // t3 zeroed at col 0
    if (jj == Wd - 1)   fac = r2v + fmaxf(fdy, 0.0f);   // t1 zeroed at col W-1
    return fac;
}

// Step 0 specialization: s=v=0 -> dep==0 exactly, terrain unchanged.
// Only writes state; terrain stays in padA.
__global__ void __launch_bounds__(256)
step0_kernel(const float* __restrict__ pin, const float* __restrict__ rain) {
    __shared__ __align__(16) float sm[(ROWS_PB + 4) * PADW];
    __shared__ __align__(16) float smr[ROWS_PB * Wd];
    __shared__ __align__(8) unsigned long long mbar;

    int blk = blockIdx.x;
    int b = blk >> 7;
    int i0 = (blk & 127) << 2;
    int t = threadIdx.x;
    int r = t >> 6;
    int q = t & 63;
    int i = i0 + r;

    uint32_t mb = smem_u32(&mbar);
    stage_tiles(pin, rain, b, i0, t, sm, smr, mb);
    wait_tiles(t, mb);

    const float4* parv = reinterpret_cast<const float4*>(g_par);
    float4 pA = parv[0];
    float4 pB = parv[1];

    const float* smc = sm + (r + 2) * PADW + 4;
    const float* smrr = smr + r * Wd;
    bool interior_i = (i > 0) && (i < Wd - 1);
    float rowsc = (i == 0) ? 1.1f : 0.9f;
    float fi = (float)i;
    int cbase = b * NPIX + i * Wd;

#pragma unroll
    for (int k = 0; k < 8; ++k) {
        int jj = q + (k << 6);
        float fdy;
        float hd = grad_gather(sm, smc, jj, i, i0, interior_i, rowsc, fi, fdy);
        float w = pA.x * smrr[jj];
        float fac = disp_fac(fdy, jj);
        int cidx = cbase + jj;
        g_sw[cidx] = make_float2(0.0f, (fac * w) * pB.z);
        g_vel[cidx] = pB.w * hd;
    }
}

template <bool LAST>
__global__ void __launch_bounds__(256)
step_kernel(const float* __restrict__ pin, float* __restrict__ pout,
            const float* __restrict__ rain, float* __restrict__ outp) {
    __shared__ __align__(16) float sm[(ROWS_PB + 4) * PADW];
    __shared__ __align__(16) float smr[ROWS_PB * Wd];
    __shared__ __align__(8) unsigned long long mbar;

    int blk = blockIdx.x;
    int b = blk >> 7;
    int i0 = (blk & 127) << 2;
    int t = threadIdx.x;
    int r = t >> 6;
    int q = t & 63;
    int i = i0 + r;

    uint32_t mb = smem_u32(&mbar);
    stage_tiles(pin, rain, b, i0, t, sm, smr, mb);

    int cbase = b * NPIX + i * Wd;

    const float4* parv = reinterpret_cast<const float4*>(g_par);
    float4 pA = parv[0];  // x=rain_rate' y=heps z=minhd w=kc'
    float4 pB = parv[1];  // x=dis y=dep z=evap' w=grav'

    // ---- first half's state loads, front-batched to overlap the TMA fills ----
    float2 sw_[4];
    float v_[4];
#pragma unroll
    for (int k = 0; k < 4; ++k) {
        int jj = q + (k << 6);
        sw_[k] = g_sw[cbase + jj];
        v_[k]  = g_vel[cbase + jj];
    }

    wait_tiles(t, mb);

    const float* smc = sm + (r + 2) * PADW + 4;
    const float* smrr = smr + r * Wd;
    bool interior_i = (i > 0) && (i < Wd - 1);
    float rowsc = (i == 0) ? 1.1f : 0.9f;
    float fi = (float)i;
    float* porow = pout + (size_t)b * PADN + (size_t)(i + 2) * PADW + 4;

#pragma unroll
    for (int half = 0; half < 2; ++half) {
        if (half == 1) {
#pragma unroll
            for (int k = 0; k < 4; ++k) {
                int jj = q + ((k + 4) << 6);
                sw_[k] = g_sw[cbase + jj];
                v_[k]  = g_vel[cbase + jj];
            }
        }

#pragma unroll
        for (int k = 0; k < 4; ++k) {
            int jj = q + ((half * 4 + k) << 6);

            float fdy;
            float hd = grad_gather(sm, smc, jj, i, i0, interior_i, rowsc, fi, fdy);
            float nhd = (hd > pA.y) ? fmaxf(hd, pA.z) : 0.0f;

            float s = sw_[k].x;
            float w = sw_[k].y + pA.x * smrr[jj];

            float scap = nhd * pA.w * v_[k] * w;
            float first = fminf(fmaxf(-hd, 0.0f), s);
            float sdiff = s - scap;
            float third = (hd < 0.0f) ? 0.0f
                        : (fmaxf(sdiff * pB.y, 0.0f) - fmaxf(-sdiff * pB.x, 0.0f));
            float dep = fmaxf(-fmaxf(hd, 0.0f), first + third);

            float s2 = s - dep;
            float t2m = smc[jj] + dep;    // = new terrain - 1

            float fac = disp_fac(fdy, jj);

            int cidx = cbase + jj;
            g_sw[cidx] = make_float2(fac * s2, (fac * w) * pB.z);
            g_vel[cidx] = pB.w * hd;
            if (LAST) {
                // relu(2 - 2*t2) - 1 == relu(-2*t2m) - 1
                outp[cidx] = fmaxf(-2.0f * t2m, 0.0f) - 1.0f;
            } else {
                porow[jj] = t2m;
            }
        }
    }
}

extern "C" void kernel_launch(void* const* d_in, const int* in_sizes, int n_in,
                              void* d_out, int out_size) {
    const float* input     = (const float*)d_in[0];
    const float* rainall   = (const float*)d_in[1];
    // d_in[2] (random_gradient) provably unused: factor == relu(1e-10 - mag) == 0 in fp32.
    const float* rain_rate = (const float*)d_in[3];
    const float* evap      = (const float*)d_in[4];
    const float* minhd     = (const float*)d_in[5];
    const float* heps      = (const float*)d_in[6];
    const float* grav      = (const float*)d_in[7];
    const float* kc        = (const float*)d_in[8];
    const float* dis       = (const float*)d_in[9];
    const float* depr      = (const float*)d_in[10];
    float* out = (float*)d_out;

    float *pA, *pB;
    cudaGetSymbolAddress((void**)&pA, g_padA);
    cudaGetSymbolAddress((void**)&pB, g_padB);

    init_kernel<<<BATCH * PADH, PADW>>>(input, rain_rate, evap, minhd, heps,
                                        grav, kc, dis, depr);

    // Step 0: dep == 0 exactly (s=v=0) -> terrain unchanged; only state produced.
    step0_kernel<<<BATCH * 128, 256>>>(pA, rainall);

    // Steps 1..9: ping-pong terrain. it=1 reads pA (still holding initial terrain).
    for (int it = 1; it < 10; ++it) {
        const float* pin = (it & 1) ? pA : pB;
        float* pout      = (it & 1) ? pB : pA;
        const float* rain = rainall + (size_t)it * NPIX;
        if (it == 9) {
            step_kernel<true><<<BATCH * 128, 256>>>(pin, pout, rain, out);
        } else {
            step_kernel<false><<<BATCH * 128, 256>>>(pin, pout, rain, out);
        }
    }
}

// round 13
// speedup vs baseline: 1.1855x; 1.0347x over previous
#include <cuda_runtime.h>
#include <cstdint>

#define Wd 512
#define BATCH 16
#define NPIX (Wd * Wd)
#define NTOT (BATCH * NPIX)
#define PADW 520
#define PADH 516
#define PADN (PADW * PADH)
#define INV_CELL 2.56f  /* 1 / (200/512) */
#define ROWS_PB 4
#define FILL_BYTES ((ROWS_PB + 4) * PADW * 4)
#define RAIN_BYTES (ROWS_PB * Wd * 4)

// Padded tm1 (= terrain - 1) buffers, zero borders.
// Logical (i,j) lives at pad[(i+2)*PADW + (j+4)].
__device__ __align__(16) float g_padA[BATCH * PADN];
__device__ __align__(16) float g_padB[BATCH * PADN];
__device__ __align__(16) float2 g_sw[NTOT];     // x=sed y=wat
__device__ __align__(16) float g_vel[NTOT];
__device__ float g_par[8];

__device__ __forceinline__ void pdl_wait() {
    asm volatile("griddepcontrol.wait;" ::: "memory");
}
__device__ __forceinline__ void pdl_launch_dependents() {
    asm volatile("griddepcontrol.launch_dependents;" ::: "memory");
}

__global__ void init_kernel(const float* __restrict__ in,
                            const float* rr, const float* ev, const float* mh,
                            const float* he, const float* gr, const float* kc,
                            const float* di, const float* de) {
    if (blockIdx.x == 0 && threadIdx.x == 0) {
        g_par[0] = fmaxf(*rr, 0.0f);            // relu(rain_rate)
        g_par[1] = *he;                         // height_epsilon
        g_par[2] = *mh;                         // min_height_delta
        g_par[3] = fmaxf(*kc, 0.0f) * INV_CELL; // relu(kc)/CELL_W
        g_par[4] = *di;                         // dissolving_rate
        g_par[5] = *de;                         // deposition_rate
        g_par[6] = 1.0f - fmaxf(*ev, 0.0f);     // 1 - relu(evap)
        g_par[7] = fmaxf(*gr, 0.0f) * INV_CELL; // relu(g)/CELL_W
    }
    int row = blockIdx.x;            // 0 .. BATCH*PADH-1
    int b = row / PADH;
    int pi = row - b * PADH;
    int pj = threadIdx.x;            // 0 .. 519
    int pidx = b * PADN + pi * PADW + pj;
    if (pi >= 2 && pi < 2 + Wd && pj >= 4 && pj < 4 + Wd) {
        int i = pi - 2, j = pj - 4;
        int cidx = b * NPIX + i * Wd + j;
        float t0 = (1.0f - in[cidx]) * 0.5f;
        g_padA[pidx] = t0 - 1.0f;            // reference's tm1, exactly
        // g_sw / g_vel written unconditionally by step0_kernel
    } else {
        // borders must be zero; interiors of B are written by step 1 before read
        g_padA[pidx] = 0.0f;
        g_padB[pidx] = 0.0f;
    }
    pdl_launch_dependents();
}

__device__ __forceinline__ uint32_t smem_u32(const void* p) {
    uint32_t a;
    asm("{ .reg .u64 t; cvta.to.shared.u64 t, %1; cvt.u32.u64 %0, t; }"
        : "=r"(a) : "l"(p));
    return a;
}

// Staging prologue: t0 owns the mbarrier end-to-end (init -> expect_tx -> TMA),
// so no pre-TMA __syncthreads is needed; wait_tiles' __syncthreads is the release.
__device__ __forceinline__ void stage_tiles(const float* pin, const float* rain,
                                            int b, int i0, int t,
                                            float* sm, float* smr, uint32_t mb) {
    if (t == 0) {
        asm volatile("mbarrier.init.shared.b64 [%0], 1;" :: "r"(mb) : "memory");
        asm volatile("mbarrier.arrive.expect_tx.shared.b64 _, [%0], %1;"
                     :: "r"(mb), "r"(FILL_BYTES + RAIN_BYTES) : "memory");
        const float* src = pin + (size_t)b * PADN + (size_t)i0 * PADW;
        asm volatile(
            "cp.async.bulk.shared::cluster.global.mbarrier::complete_tx::bytes "
            "[%0], [%1], %2, [%3];"
            :: "r"(smem_u32(sm)), "l"(src), "r"(FILL_BYTES), "r"(mb) : "memory");
        const float* rsrc = rain + (size_t)i0 * Wd;
        asm volatile(
            "cp.async.bulk.shared::cluster.global.mbarrier::complete_tx::bytes "
            "[%0], [%1], %2, [%3];"
            :: "r"(smem_u32(smr)), "l"(rsrc), "r"(RAIN_BYTES), "r"(mb) : "memory");
    }
}

__device__ __forceinline__ void wait_tiles(int t, uint32_t mb) {
    // only t0 polls (HW-sleep); everyone else parks at the barrier
    if (t == 0) {
        uint32_t done = 0;
        while (!done) {
            asm volatile(
                "{ .reg .pred p; mbarrier.try_wait.parity.shared.b64 p, [%1], 0, 0x989680; "
                "selp.u32 %0, 1, 0, p; }"
                : "=r"(done) : "r"(mb) : "memory");
        }
    }
    __syncthreads();
}

// Gradient + bilinear gather (tm1-space). Returns hd; writes fdy.
__device__ __forceinline__ float grad_gather(const float* sm, const float* smc,
                                             int jj, int i, int i0,
                                             bool interior_i, float rowsc,
                                             float fi, float& fdy_out) {
    float tcm = smc[jj];

    float dx;
    if (interior_i) {
        dx = 0.5f * (smc[jj + PADW] - smc[jj - PADW]);
    } else {
        float tcf = tcm + 1.0f;
        dx = 0.5f * (tcf * rowsc - tcf);
    }

    float dy;
    if (jj == 0) {
        float tcf = tcm + 1.0f;
        dy = 0.5f * (tcf * 1.1f - tcf);
    } else if (jj == Wd - 1) {
        float tcf = tcm + 1.0f;
        dy = 0.5f * (tcf * 0.9f - tcf);
    } else {
        dy = 0.5f * (smc[jj + 1] - smc[jj - 1]);
    }

    float rinv = rsqrtf(dx * dx + dy * dy + 1e-11f);
    float fdx = dx * rinv;
    float fdy = dy * rinv;
    fdy_out = fdy;

    float fx = (float)jj - fdx;
    float fy = fi - fdy;
    float x0 = floorf(fx), y0 = floorf(fy);
    float wx = fx - x0, wy = fy - y0;
    int ix = (int)x0;
    int iy = (int)y0;

    const float* g = sm + (iy - i0 + 2) * PADW + (ix + 4);
    float g00 = g[0];
    float g10 = g[1];
    float g01 = g[PADW];
    float g11 = g[PADW + 1];
    float nbm = (1.0f - wy) * ((1.0f - wx) * g00 + wx * g10)
              + wy          * ((1.0f - wx) * g01 + wx * g11);

    return tcm - nbm;
}

__device__ __forceinline__ float disp_fac(float fdy, int jj) {
    float ad = fabsf(fdy);
    float r2v = fmaxf(1.0f - ad, 0.0f);
    float fac = ad + r2v;
    if (jj == 0)        fac = fmaxf(-fdy, 0.0f) + r2v;  // t3 zeroed at col 0
    if (jj == Wd - 1)   fac = r2v + fmaxf(fdy, 0.0f);   // t1 zeroed at col W-1
    return fac;
}

// Step 0 specialization: s=v=0 -> dep==0 exactly, terrain unchanged.
__global__ void __launch_bounds__(256)
step0_kernel(const float* __restrict__ pin, const float* __restrict__ rain) {
    __shared__ __align__(16) float sm[(ROWS_PB + 4) * PADW];
    __shared__ __align__(16) float smr[ROWS_PB * Wd];
    __shared__ __align__(8) unsigned long long mbar;

    int blk = blockIdx.x;
    int b = blk >> 7;
    int i0 = (blk & 127) << 2;
    int t = threadIdx.x;
    int r = t >> 6;
    int q = t & 63;
    int i = i0 + r;

    uint32_t mb = smem_u32(&mbar);
    pdl_wait();                    // predecessor (init) must have written padA
    stage_tiles(pin, rain, b, i0, t, sm, smr, mb);
    wait_tiles(t, mb);

    const float4* parv = reinterpret_cast<const float4*>(g_par);
    float4 pA = parv[0];
    float4 pB = parv[1];

    const float* smc = sm + (r + 2) * PADW + 4;
    const float* smrr = smr + r * Wd;
    bool interior_i = (i > 0) && (i < Wd - 1);
    float rowsc = (i == 0) ? 1.1f : 0.9f;
    float fi = (float)i;
    int cbase = b * NPIX + i * Wd;

#pragma unroll
    for (int k = 0; k < 8; ++k) {
        int jj = q + (k << 6);
        float fdy;
        float hd = grad_gather(sm, smc, jj, i, i0, interior_i, rowsc, fi, fdy);
        float w = pA.x * smrr[jj];
        float fac = disp_fac(fdy, jj);
        int cidx = cbase + jj;
        g_sw[cidx] = make_float2(0.0f, (fac * w) * pB.z);
        g_vel[cidx] = pB.w * hd;
    }
    pdl_launch_dependents();
}

template <bool LAST>
__global__ void __launch_bounds__(256)
step_kernel(const float* __restrict__ pin, float* __restrict__ pout,
            const float* __restrict__ rain, float* __restrict__ outp) {
    __shared__ __align__(16) float sm[(ROWS_PB + 4) * PADW];
    __shared__ __align__(16) float smr[ROWS_PB * Wd];
    __shared__ __align__(8) unsigned long long mbar;

    int blk = blockIdx.x;
    int b = blk >> 7;
    int i0 = (blk & 127) << 2;
    int t = threadIdx.x;
    int r = t >> 6;
    int q = t & 63;
    int i = i0 + r;

    uint32_t mb = smem_u32(&mbar);
    pdl_wait();                    // predecessor's terrain/state writes must be visible
    stage_tiles(pin, rain, b, i0, t, sm, smr, mb);

    int cbase = b * NPIX + i * Wd;

    const float4* parv = reinterpret_cast<const float4*>(g_par);
    float4 pA = parv[0];  // x=rain_rate' y=heps z=minhd w=kc'
    float4 pB = parv[1];  // x=dis y=dep z=evap' w=grav'

    // ---- first half's state loads, front-batched to overlap the TMA fills ----
    float2 sw_[4];
    float v_[4];
#pragma unroll
    for (int k = 0; k < 4; ++k) {
        int jj = q + (k << 6);
        sw_[k] = g_sw[cbase + jj];
        v_[k]  = g_vel[cbase + jj];
    }

    wait_tiles(t, mb);

    const float* smc = sm + (r + 2) * PADW + 4;
    const float* smrr = smr + r * Wd;
    bool interior_i = (i > 0) && (i < Wd - 1);
    float rowsc = (i == 0) ? 1.1f : 0.9f;
    float fi = (float)i;
    float* porow = pout + (size_t)b * PADN + (size_t)(i + 2) * PADW + 4;

#pragma unroll
    for (int half = 0; half < 2; ++half) {
        if (half == 1) {
#pragma unroll
            for (int k = 0; k < 4; ++k) {
                int jj = q + ((k + 4) << 6);
                sw_[k] = g_sw[cbase + jj];
                v_[k]  = g_vel[cbase + jj];
            }
        }

#pragma unroll
        for (int k = 0; k < 4; ++k) {
            int jj = q + ((half * 4 + k) << 6);

            float fdy;
            float hd = grad_gather(sm, smc, jj, i, i0, interior_i, rowsc, fi, fdy);
            float nhd = (hd > pA.y) ? fmaxf(hd, pA.z) : 0.0f;

            float s = sw_[k].x;
            float w = sw_[k].y + pA.x * smrr[jj];

            float scap = nhd * pA.w * v_[k] * w;
            float first = fminf(fmaxf(-hd, 0.0f), s);
            float sdiff = s - scap;
            float third = (hd < 0.0f) ? 0.0f
                        : (fmaxf(sdiff * pB.y, 0.0f) - fmaxf(-sdiff * pB.x, 0.0f));
            float dep = fmaxf(-fmaxf(hd, 0.0f), first + third);

            float s2 = s - dep;
            float t2m = smc[jj] + dep;    // = new terrain - 1

            float fac = disp_fac(fdy, jj);

            int cidx = cbase + jj;
            g_sw[cidx] = make_float2(fac * s2, (fac * w) * pB.z);
            g_vel[cidx] = pB.w * hd;
            if (LAST) {
                // relu(2 - 2*t2) - 1 == relu(-2*t2m) - 1
                outp[cidx] = fmaxf(-2.0f * t2m, 0.0f) - 1.0f;
            } else {
                porow[jj] = t2m;
            }
        }
    }
    pdl_launch_dependents();
}

template <typename F, typename... Args>
static inline void launch_pdl(F fn, dim3 g, dim3 b, Args... args) {
    cudaLaunchConfig_t cfg = {};
    cfg.gridDim = g;
    cfg.blockDim = b;
    cfg.dynamicSmemBytes = 0;
    cfg.stream = 0;   // default stream (harness captures it)
    cudaLaunchAttribute at[1];
    at[0].id = cudaLaunchAttributeProgrammaticStreamSerialization;
    at[0].val.programmaticStreamSerializationAllowed = 1;
    cfg.attrs = at;
    cfg.numAttrs = 1;
    cudaLaunchKernelEx(&cfg, fn, args...);
}

extern "C" void kernel_launch(void* const* d_in, const int* in_sizes, int n_in,
                              void* d_out, int out_size) {
    const float* input     = (const float*)d_in[0];
    const float* rainall   = (const float*)d_in[1];
    // d_in[2] (random_gradient) provably unused: factor == relu(1e-10 - mag) == 0 in fp32.
    const float* rain_rate = (const float*)d_in[3];
    const float* evap      = (const float*)d_in[4];
    const float* minhd     = (const float*)d_in[5];
    const float* heps      = (const float*)d_in[6];
    const float* grav      = (const float*)d_in[7];
    const float* kc        = (const float*)d_in[8];
    const float* dis       = (const float*)d_in[9];
    const float* depr      = (const float*)d_in[10];
    float* out = (float*)d_out;

    float *pA, *pB;
    cudaGetSymbolAddress((void**)&pA, g_padA);
    cudaGetSymbolAddress((void**)&pB, g_padB);

    init_kernel<<<BATCH * PADH, PADW>>>(input, rain_rate, evap, minhd, heps,
                                        grav, kc, dis, depr);

    // Step 0: dep == 0 exactly (s=v=0) -> terrain unchanged; only state produced.
    launch_pdl(step0_kernel, dim3(BATCH * 128), dim3(256),
               (const float*)pA, rainall);

    // Steps 1..9: ping-pong terrain. it=1 reads pA (still holding initial terrain).
    for (int it = 1; it < 10; ++it) {
        const float* pin = (it & 1) ? pA : pB;
        float* pout      = (it & 1) ? pB : pA;
        const float* rain = rainall + (size_t)it * NPIX;
        if (it == 9) {
            launch_pdl(step_kernel<true>, dim3(BATCH * 128), dim3(256),
                       pin, pout, rain, out);
        } else {
            launch_pdl(step_kernel<false>, dim3(BATCH * 128), dim3(256),
                       pin, pout, rain, out);
        }
    }
}

// round 14
// speedup vs baseline: 1.2079x; 1.0188x over previous
#include <cuda_runtime.h>
#include <cstdint>

#define Wd 512
#define BATCH 16
#define NPIX (Wd * Wd)
#define NTOT (BATCH * NPIX)
#define PADW 520
#define PADH 516
#define PADN (PADW * PADH)
#define INV_CELL 2.56f  /* 1 / (200/512) */
#define ROWS_PB 4
#define FILL_BYTES ((ROWS_PB + 4) * PADW * 4)
#define RAIN_BYTES (ROWS_PB * Wd * 4)

// Padded tm1 (= terrain - 1) buffers, zero borders.
// Logical (i,j) lives at pad[(i+2)*PADW + (j+4)].
__device__ __align__(16) float g_padA[BATCH * PADN];
__device__ __align__(16) float g_padB[BATCH * PADN];
__device__ __align__(16) float2 g_sw[NTOT];     // x=sed y=wat
__device__ __align__(16) float g_vel[NTOT];
__device__ float g_par[8];

__device__ __forceinline__ void pdl_wait() {
    asm volatile("griddepcontrol.wait;" ::: "memory");
}
__device__ __forceinline__ void pdl_launch_dependents() {
    asm volatile("griddepcontrol.launch_dependents;" ::: "memory");
}

__global__ void init_kernel(const float* __restrict__ in,
                            const float* rr, const float* ev, const float* mh,
                            const float* he, const float* gr, const float* kc,
                            const float* di, const float* de) {
    if (blockIdx.x == 0 && threadIdx.x == 0) {
        g_par[0] = fmaxf(*rr, 0.0f);            // relu(rain_rate)
        g_par[1] = *he;                         // height_epsilon
        g_par[2] = *mh;                         // min_height_delta
        g_par[3] = fmaxf(*kc, 0.0f) * INV_CELL; // relu(kc)/CELL_W
        g_par[4] = *di;                         // dissolving_rate
        g_par[5] = *de;                         // deposition_rate
        g_par[6] = 1.0f - fmaxf(*ev, 0.0f);     // 1 - relu(evap)
        g_par[7] = fmaxf(*gr, 0.0f) * INV_CELL; // relu(g)/CELL_W
    }
    int row = blockIdx.x;            // 0 .. BATCH*PADH-1
    int b = row / PADH;
    int pi = row - b * PADH;
    int pj = threadIdx.x;            // 0 .. 519
    int pidx = b * PADN + pi * PADW + pj;
    if (pi >= 2 && pi < 2 + Wd && pj >= 4 && pj < 4 + Wd) {
        int i = pi - 2, j = pj - 4;
        int cidx = b * NPIX + i * Wd + j;
        float t0 = (1.0f - in[cidx]) * 0.5f;
        g_padA[pidx] = t0 - 1.0f;            // reference's tm1, exactly
        // g_sw / g_vel written unconditionally by step0_kernel
    } else {
        // borders must be zero; interiors of B are written by step 1 before read
        g_padA[pidx] = 0.0f;
        g_padB[pidx] = 0.0f;
    }
    pdl_launch_dependents();
}

__device__ __forceinline__ uint32_t smem_u32(const void* p) {
    uint32_t a;
    asm("{ .reg .u64 t; cvta.to.shared.u64 t, %1; cvt.u32.u64 %0, t; }"
        : "=r"(a) : "l"(p));
    return a;
}

// Staging prologue: t0 owns the mbarrier end-to-end (init -> expect_tx -> TMA),
// so no pre-TMA __syncthreads is needed; wait_tiles' __syncthreads is the release.
__device__ __forceinline__ void stage_tiles(const float* pin, const float* rain,
                                            int b, int i0, int t,
                                            float* sm, float* smr, uint32_t mb) {
    if (t == 0) {
        asm volatile("mbarrier.init.shared.b64 [%0], 1;" :: "r"(mb) : "memory");
        asm volatile("mbarrier.arrive.expect_tx.shared.b64 _, [%0], %1;"
                     :: "r"(mb), "r"(FILL_BYTES + RAIN_BYTES) : "memory");
        const float* src = pin + (size_t)b * PADN + (size_t)i0 * PADW;
        asm volatile(
            "cp.async.bulk.shared::cluster.global.mbarrier::complete_tx::bytes "
            "[%0], [%1], %2, [%3];"
            :: "r"(smem_u32(sm)), "l"(src), "r"(FILL_BYTES), "r"(mb) : "memory");
        const float* rsrc = rain + (size_t)i0 * Wd;
        asm volatile(
            "cp.async.bulk.shared::cluster.global.mbarrier::complete_tx::bytes "
            "[%0], [%1], %2, [%3];"
            :: "r"(smem_u32(smr)), "l"(rsrc), "r"(RAIN_BYTES), "r"(mb) : "memory");
    }
}

__device__ __forceinline__ void wait_tiles(int t, uint32_t mb) {
    // only t0 polls (HW-sleep); everyone else parks at the barrier
    if (t == 0) {
        uint32_t done = 0;
        while (!done) {
            asm volatile(
                "{ .reg .pred p; mbarrier.try_wait.parity.shared.b64 p, [%1], 0, 0x989680; "
                "selp.u32 %0, 1, 0, p; }"
                : "=r"(done) : "r"(mb) : "memory");
        }
    }
    __syncthreads();
}

// Gradient + bilinear gather (tm1-space). Returns hd; writes fdy.
__device__ __forceinline__ float grad_gather(const float* sm, const float* smc,
                                             int jj, int i, int i0,
                                             bool interior_i, float rowsc,
                                             float fi, float& fdy_out) {
    float tcm = smc[jj];

    float dx;
    if (interior_i) {
        dx = 0.5f * (smc[jj + PADW] - smc[jj - PADW]);
    } else {
        float tcf = tcm + 1.0f;
        dx = 0.5f * (tcf * rowsc - tcf);
    }

    float dy;
    if (jj == 0) {
        float tcf = tcm + 1.0f;
        dy = 0.5f * (tcf * 1.1f - tcf);
    } else if (jj == Wd - 1) {
        float tcf = tcm + 1.0f;
        dy = 0.5f * (tcf * 0.9f - tcf);
    } else {
        dy = 0.5f * (smc[jj + 1] - smc[jj - 1]);
    }

    float rinv = rsqrtf(dx * dx + dy * dy + 1e-11f);
    float fdx = dx * rinv;
    float fdy = dy * rinv;
    fdy_out = fdy;

    float fx = (float)jj - fdx;
    float fy = fi - fdy;
    float x0 = floorf(fx), y0 = floorf(fy);
    float wx = fx - x0, wy = fy - y0;
    int ix = (int)x0;
    int iy = (int)y0;

    const float* g = sm + (iy - i0 + 2) * PADW + (ix + 4);
    float g00 = g[0];
    float g10 = g[1];
    float g01 = g[PADW];
    float g11 = g[PADW + 1];
    float nbm = (1.0f - wy) * ((1.0f - wx) * g00 + wx * g10)
              + wy          * ((1.0f - wx) * g01 + wx * g11);

    return tcm - nbm;
}

__device__ __forceinline__ float disp_fac(float fdy, int jj) {
    float ad = fabsf(fdy);
    float r2v = fmaxf(1.0f - ad, 0.0f);
    float fac = ad + r2v;
    if (jj == 0)        fac = fmaxf(-fdy, 0.0f) + r2v;  // t3 zeroed at col 0
    if (jj == Wd - 1)   fac = r2v + fmaxf(fdy, 0.0f);   // t1 zeroed at col W-1
    return fac;
}

// Step 0 specialization: s=v=0 -> dep==0 exactly, terrain unchanged.
__global__ void __launch_bounds__(256)
step0_kernel(const float* __restrict__ pin, const float* __restrict__ rain) {
    __shared__ __align__(16) float sm[(ROWS_PB + 4) * PADW];
    __shared__ __align__(16) float smr[ROWS_PB * Wd];
    __shared__ __align__(8) unsigned long long mbar;

    int blk = blockIdx.x;
    int b = blk >> 7;
    int i0 = (blk & 127) << 2;
    int t = threadIdx.x;
    int r = t >> 6;
    int q = t & 63;
    int i = i0 + r;

    uint32_t mb = smem_u32(&mbar);
    pdl_wait();                    // predecessor (init) must have written padA
    stage_tiles(pin, rain, b, i0, t, sm, smr, mb);
    wait_tiles(t, mb);

    const float4* parv = reinterpret_cast<const float4*>(g_par);
    float4 pA = parv[0];
    float4 pB = parv[1];

    const float* smc = sm + (r + 2) * PADW + 4;
    const float* smrr = smr + r * Wd;
    bool interior_i = (i > 0) && (i < Wd - 1);
    float rowsc = (i == 0) ? 1.1f : 0.9f;
    float fi = (float)i;
    int cbase = b * NPIX + i * Wd;

#pragma unroll
    for (int k = 0; k < 8; ++k) {
        int jj = q + (k << 6);
        float fdy;
        float hd = grad_gather(sm, smc, jj, i, i0, interior_i, rowsc, fi, fdy);
        float w = pA.x * smrr[jj];
        float fac = disp_fac(fdy, jj);
        int cidx = cbase + jj;
        g_sw[cidx] = make_float2(0.0f, (fac * w) * pB.z);
        g_vel[cidx] = pB.w * hd;
    }
    pdl_launch_dependents();
}

template <bool LAST>
__global__ void __launch_bounds__(256)
step_kernel(const float* __restrict__ pin, float* __restrict__ pout,
            const float* __restrict__ rain, float* __restrict__ outp) {
    __shared__ __align__(16) float sm[(ROWS_PB + 4) * PADW];
    __shared__ __align__(16) float smr[ROWS_PB * Wd];
    __shared__ __align__(8) unsigned long long mbar;

    int blk = blockIdx.x;
    int b = blk >> 7;
    int i0 = (blk & 127) << 2;
    int t = threadIdx.x;
    int r = t >> 6;
    int q = t & 63;
    int i = i0 + r;

    uint32_t mb = smem_u32(&mbar);
    pdl_wait();                    // predecessor's terrain/state writes must be visible
    stage_tiles(pin, rain, b, i0, t, sm, smr, mb);

    int cbase = b * NPIX + i * Wd;

    const float4* parv = reinterpret_cast<const float4*>(g_par);
    float4 pA = parv[0];  // x=rain_rate' y=heps z=minhd w=kc'
    float4 pB = parv[1];  // x=dis y=dep z=evap' w=grav'

    // ---- first half's state loads, front-batched to overlap the TMA fills ----
    float2 sw_[4];
    float v_[4];
#pragma unroll
    for (int k = 0; k < 4; ++k) {
        int jj = q + (k << 6);
        sw_[k] = g_sw[cbase + jj];
        v_[k]  = g_vel[cbase + jj];
    }

    wait_tiles(t, mb);

    const float* smc = sm + (r + 2) * PADW + 4;
    const float* smrr = smr + r * Wd;
    bool interior_i = (i > 0) && (i < Wd - 1);
    float rowsc = (i == 0) ? 1.1f : 0.9f;
    float fi = (float)i;
    float* porow = pout + (size_t)b * PADN + (size_t)(i + 2) * PADW + 4;

#pragma unroll
    for (int half = 0; half < 2; ++half) {
        if (half == 1) {
#pragma unroll
            for (int k = 0; k < 4; ++k) {
                int jj = q + ((k + 4) << 6);
                sw_[k] = g_sw[cbase + jj];
                v_[k]  = g_vel[cbase + jj];
            }
        }

#pragma unroll
        for (int k = 0; k < 4; ++k) {
            int jj = q + ((half * 4 + k) << 6);

            float fdy;
            float hd = grad_gather(sm, smc, jj, i, i0, interior_i, rowsc, fi, fdy);
            float nhd = (hd > pA.y) ? fmaxf(hd, pA.z) : 0.0f;

            float s = sw_[k].x;
            float w = sw_[k].y + pA.x * smrr[jj];

            float scap = nhd * pA.w * v_[k] * w;
            float first = fminf(fmaxf(-hd, 0.0f), s);
            float sdiff = s - scap;
            float third = (hd < 0.0f) ? 0.0f
                        : (fmaxf(sdiff * pB.y, 0.0f) - fmaxf(-sdiff * pB.x, 0.0f));
            float dep = fmaxf(-fmaxf(hd, 0.0f), first + third);

            float t2m = smc[jj] + dep;    // = new terrain - 1

            if (LAST) {
                // Post-step-9 state is dead: skip displacement + all state stores.
                // relu(2 - 2*t2) - 1 == relu(-2*t2m) - 1
                outp[cbase + jj] = fmaxf(-2.0f * t2m, 0.0f) - 1.0f;
            } else {
                float s2 = s - dep;
                float fac = disp_fac(fdy, jj);
                int cidx = cbase + jj;
                g_sw[cidx] = make_float2(fac * s2, (fac * w) * pB.z);
                g_vel[cidx] = pB.w * hd;
                porow[jj] = t2m;
            }
        }
    }
    pdl_launch_dependents();
}

template <typename F, typename... Args>
static inline void launch_pdl(F fn, dim3 g, dim3 b, Args... args) {
    cudaLaunchConfig_t cfg = {};
    cfg.gridDim = g;
    cfg.blockDim = b;
    cfg.dynamicSmemBytes = 0;
    cfg.stream = 0;   // default stream (harness captures it)
    cudaLaunchAttribute at[1];
    at[0].id = cudaLaunchAttributeProgrammaticStreamSerialization;
    at[0].val.programmaticStreamSerializationAllowed = 1;
    cfg.attrs = at;
    cfg.numAttrs = 1;
    cudaLaunchKernelEx(&cfg, fn, args...);
}

extern "C" void kernel_launch(void* const* d_in, const int* in_sizes, int n_in,
                              void* d_out, int out_size) {
    const float* input     = (const float*)d_in[0];
    const float* rainall   = (const float*)d_in[1];
    // d_in[2] (random_gradient) provably unused: factor == relu(1e-10 - mag) == 0 in fp32.
    const float* rain_rate = (const float*)d_in[3];
    const float* evap      = (const float*)d_in[4];
    const float* minhd     = (const float*)d_in[5];
    const float* heps      = (const float*)d_in[6];
    const float* grav      = (const float*)d_in[7];
    const float* kc        = (const float*)d_in[8];
    const float* dis       = (const float*)d_in[9];
    const float* depr      = (const float*)d_in[10];
    float* out = (float*)d_out;

    float *pA, *pB;
    cudaGetSymbolAddress((void**)&pA, g_padA);
    cudaGetSymbolAddress((void**)&pB, g_padB);

    init_kernel<<<BATCH * PADH, PADW>>>(input, rain_rate, evap, minhd, heps,
                                        grav, kc, dis, depr);

    // Step 0: dep == 0 exactly (s=v=0) -> terrain unchanged; only state produced.
    launch_pdl(step0_kernel, dim3(BATCH * 128), dim3(256),
               (const float*)pA, rainall);

    // Steps 1..9: ping-pong terrain. it=1 reads pA (still holding initial terrain).
    for (int it = 1; it < 10; ++it) {
        const float* pin = (it & 1) ? pA : pB;
        float* pout      = (it & 1) ? pB : pA;
        const float* rain = rainall + (size_t)it * NPIX;
        if (it == 9) {
            launch_pdl(step_kernel<true>, dim3(BATCH * 128), dim3(256),
                       pin, pout, rain, out);
        } else {
            launch_pdl(step_kernel<false>, dim3(BATCH * 128), dim3(256),
                       pin, pout, rain, out);
        }
    }
}